// round 15
// baseline (speedup 1.0000x reference)
#include <cuda_runtime.h>
#include <cuda_bf16.h>
#include <cuda_fp16.h>
#include <math.h>
#include <stdint.h>

// Problem constants
#define NB     64
#define LL     196
#define HID    768
#define FF     3072
#define NH     24
#define HD     32
#define M_ROWS (NB * LL)          // 12544
#define RATE_F 0.2f
#define LPAD   208

// ---------------- scratch (static device globals; no runtime allocation) ----
__device__ __half g_qh[(size_t)M_ROWS * HID];
__device__ __half g_kh[(size_t)M_ROWS * HID];
__device__ __half g_vh[(size_t)M_ROWS * HID];
__device__ __half g_oh [(size_t)M_ROWS * HID];
__device__ __half g_lnh[(size_t)M_ROWS * HID];
__device__ __half g_hh [(size_t)M_ROWS * FF];
__device__ __half g_wouth[HID * HID];
__device__ __half g_w1h[FF * HID];
__device__ __half g_w2h[HID * FF];
__device__ float  g_bias[LPAD * LPAD];

// ------------------------------------------------------------ helpers
__device__ __forceinline__ void mma_fp16(
    float* c, uint32_t a0, uint32_t a1, uint32_t a2, uint32_t a3,
    uint32_t b0, uint32_t b1)
{
    asm volatile(
        "mma.sync.aligned.m16n8k16.row.col.f32.f16.f16.f32 "
        "{%0,%1,%2,%3}, {%4,%5,%6,%7}, {%8,%9}, {%0,%1,%2,%3};\n"
        : "+f"(c[0]), "+f"(c[1]), "+f"(c[2]), "+f"(c[3])
        : "r"(a0), "r"(a1), "r"(a2), "r"(a3), "r"(b0), "r"(b1));
}
__device__ __forceinline__ uint32_t h2u(float lo, float hi) {
    __half2 h = __floats2half2_rn(lo, hi);
    return *reinterpret_cast<uint32_t*>(&h);
}

#define CP_ASYNC16(dst, src) \
    asm volatile("cp.async.cg.shared.global [%0], [%1], 16;\n" :: "r"(dst), "l"(src))

#define LDSM_X4(r, addr) \
    asm volatile("ldmatrix.sync.aligned.m8n8.x4.shared.b16 {%0,%1,%2,%3}, [%4];" \
        : "=r"((r)[0]), "=r"((r)[1]), "=r"((r)[2]), "=r"((r)[3]) : "r"(addr))

// ------------------------------------------- fused prep (weights + bias mat)
#define NW0 (HID * HID)
#define NW1 (FF * HID)
#define NW2 (HID * FF)
#define NPREP (NW0 + NW1 + NW2 + LPAD * LPAD)

__global__ __launch_bounds__(256) void prep_kernel(
    const float* __restrict__ w_out, const float* __restrict__ w1,
    const float* __restrict__ w2, const float* __restrict__ rel_bias,
    __half* __restrict__ wouth, __half* __restrict__ w1h,
    __half* __restrict__ w2h, float* __restrict__ bm)
{
    int i = blockIdx.x * 256 + threadIdx.x;
    if (i < NW0) { wouth[i] = __float2half_rn(w_out[i]); return; }
    i -= NW0;
    if (i < NW1) { w1h[i] = __float2half_rn(w1[i]); return; }
    i -= NW1;
    if (i < NW2) { w2h[i] = __float2half_rn(w2[i]); return; }
    i -= NW2;
    if (i < LPAD * LPAD) {
        int row = i / LPAD, col = i % LPAD;
        float val = 0.f;
        if (row < LL && col < LL) {
            int qi = row / 14, qj = row % 14;
            int ki = col / 14, kj = col % 14;
            val = rel_bias[(qi - ki + 14) * 28 + (qj - kj + 14)];
        }
        bm[i] = val;
    }
}

// --------------------------------------------- LayerNorm (fp16 out for GEMM)
__global__ __launch_bounds__(256) void ln_kernel(
    const float* __restrict__ x, const float* __restrict__ g,
    const float* __restrict__ b, __half* __restrict__ y)
{
    __shared__ float sm8[8];
    __shared__ float sstat;
    const int row = blockIdx.x, tid = threadIdx.x;
    const float* xr = x + (size_t)row * HID;
    float v0 = xr[tid], v1 = xr[tid + 256], v2 = xr[tid + 512];
    float s = v0 + v1 + v2;
    #pragma unroll
    for (int off = 16; off; off >>= 1) s += __shfl_xor_sync(0xffffffffu, s, off);
    if ((tid & 31) == 0) sm8[tid >> 5] = s;
    __syncthreads();
    if (tid == 0) {
        float t = 0.f;
        #pragma unroll
        for (int i = 0; i < 8; i++) t += sm8[i];
        sstat = t * (1.0f / HID);
    }
    __syncthreads();
    const float mu = sstat;
    float d0 = v0 - mu, d1 = v1 - mu, d2 = v2 - mu;
    float q = d0 * d0 + d1 * d1 + d2 * d2;
    #pragma unroll
    for (int off = 16; off; off >>= 1) q += __shfl_xor_sync(0xffffffffu, q, off);
    __syncthreads();
    if ((tid & 31) == 0) sm8[tid >> 5] = q;
    __syncthreads();
    if (tid == 0) {
        float t = 0.f;
        #pragma unroll
        for (int i = 0; i < 8; i++) t += sm8[i];
        sstat = rsqrtf(t * (1.0f / HID) + 1e-5f);
    }
    __syncthreads();
    const float r = sstat;
    __half* yr = y + (size_t)row * HID;
    yr[tid]       = __float2half_rn(d0 * r * g[tid]       + b[tid]);
    yr[tid + 256] = __float2half_rn(d1 * r * g[tid + 256] + b[tid + 256]);
    yr[tid + 512] = __float2half_rn(d2 * r * g[tid + 512] + b[tid + 512]);
}

// ------------------------------------------ fused LayerNorm1 + QKV (fp16 out)
__global__ __launch_bounds__(256) void ln_qkv_kernel(
    const float* __restrict__ x, const float* __restrict__ g,
    const float* __restrict__ b,
    const float* __restrict__ wq, const float* __restrict__ wk,
    const float* __restrict__ wv,
    __half* __restrict__ q, __half* __restrict__ k_, __half* __restrict__ v)
{
    __shared__ float xs[HID];
    __shared__ float ws[3][32][33];
    __shared__ float sm8[8];
    __shared__ float sstat;
    const int row = blockIdx.x, tid = threadIdx.x;

    for (int t = tid; t < 1024; t += 256) {
        const int e = t >> 5, d = t & 31;
        ws[0][e][d] = wq[t];
        ws[1][e][d] = wk[t];
        ws[2][e][d] = wv[t];
    }

    const float* xr = x + (size_t)row * HID;
    float v0 = xr[tid], v1 = xr[tid + 256], v2 = xr[tid + 512];
    float s = v0 + v1 + v2;
    #pragma unroll
    for (int off = 16; off; off >>= 1) s += __shfl_xor_sync(0xffffffffu, s, off);
    if ((tid & 31) == 0) sm8[tid >> 5] = s;
    __syncthreads();
    if (tid == 0) {
        float t = 0.f;
        #pragma unroll
        for (int i = 0; i < 8; i++) t += sm8[i];
        sstat = t * (1.0f / HID);
    }
    __syncthreads();
    const float mu = sstat;
    float d0 = v0 - mu, d1 = v1 - mu, d2 = v2 - mu;
    float qq = d0 * d0 + d1 * d1 + d2 * d2;
    #pragma unroll
    for (int off = 16; off; off >>= 1) qq += __shfl_xor_sync(0xffffffffu, qq, off);
    __syncthreads();
    if ((tid & 31) == 0) sm8[tid >> 5] = qq;
    __syncthreads();
    if (tid == 0) {
        float t = 0.f;
        #pragma unroll
        for (int i = 0; i < 8; i++) t += sm8[i];
        sstat = rsqrtf(t * (1.0f / HID) + 1e-5f);
    }
    __syncthreads();
    const float r = sstat;
    xs[tid]       = d0 * r * g[tid]       + b[tid];
    xs[tid + 256] = d1 * r * g[tid + 256] + b[tid + 256];
    xs[tid + 512] = d2 * r * g[tid + 512] + b[tid + 512];
    __syncthreads();

    for (int t = tid; t < 3 * HID; t += 256) {
        const int m = t / HID, rr = t % HID;
        const int hh = rr >> 5, e = rr & 31;
        const float* xp = xs + (hh << 5);
        const float* wp = &ws[m][e][0];
        float acc = 0.f;
        #pragma unroll
        for (int d = 0; d < 32; d++) acc = fmaf(xp[d], wp[d], acc);
        __half* out = (m == 0) ? q : ((m == 1) ? k_ : v);
        out[(size_t)row * HID + rr] = __float2half_rn(acc);
    }
}

// ------------------------------------------------ fp16 tensor-core attention
#define QKS  20    // uint32 stride per qs/ks row (40 halves)
#define VTS5 108   // uint32 stride per vT row (216 halves)

__global__ __launch_bounds__(128, 3) void attn_fp16_kernel(
    const __half* __restrict__ q, const __half* __restrict__ k,
    const __half* __restrict__ v, const float* __restrict__ bias_mat,
    __half* __restrict__ o)
{
    extern __shared__ uint32_t smA[];
    uint32_t* qs = smA;
    uint32_t* ks = qs + LPAD * QKS;
    uint32_t* vT = ks + LPAD * QKS;

    const int nb = blockIdx.x;
    const int n = nb / NH, h = nb % NH;
    const int tid = threadIdx.x, lane = tid & 31, warp = tid >> 5;
    const size_t base = (size_t)n * LL * HID + (size_t)h * HD;

    {
        const uint32_t* qg = (const uint32_t*)(q + base);
        const uint32_t* kg = (const uint32_t*)(k + base);
        for (int t = tid; t < LL * 16; t += 128) {
            const int l = t >> 4, dp = t & 15;
            qs[l * QKS + dp] = qg[l * (HID / 2) + dp];
            ks[l * QKS + dp] = kg[l * (HID / 2) + dp];
        }
        __half* vh = (__half*)vT;
        for (int t = tid; t < LL * HD; t += 128) {
            const int l = t >> 5, d = t & 31;
            vh[d * 216 + l] = v[base + (size_t)l * HID + d];
        }
        for (int t = tid; t < 12 * 16; t += 128)
            qs[(LL + (t >> 4)) * QKS + (t & 15)] = 0;
        for (int t = tid; t < 32 * 12; t += 128)
            vh[(t / 12) * 216 + LL + (t % 12)] = __float2half_rn(0.f);
    }
    __syncthreads();

    const float scale = 0.17677669529663687f;
    const int r = lane >> 2, jq = lane & 3;

    for (int mt = warp; mt < 13; mt += 4) {
        const int row0 = mt * 16 + r;

        float sacc[26][4];
        #pragma unroll
        for (int nt = 0; nt < 26; nt++)
            #pragma unroll
            for (int e = 0; e < 4; e++) sacc[nt][e] = 0.f;

        #pragma unroll
        for (int kt = 0; kt < 2; kt++) {
            const int kb = kt * 8 + jq;
            const uint32_t a0 = qs[row0 * QKS + kb];
            const uint32_t a1 = qs[(row0 + 8) * QKS + kb];
            const uint32_t a2 = qs[row0 * QKS + kb + 4];
            const uint32_t a3 = qs[(row0 + 8) * QKS + kb + 4];
            #pragma unroll
            for (int nt = 0; nt < 26; nt++) {
                const int kr = (nt * 8 + r) * QKS + kb;
                const uint32_t b0 = ks[kr];
                const uint32_t b1 = ks[kr + 4];
                mma_fp16(sacc[nt], a0, a1, a2, a3, b0, b1);
            }
        }

        float mx0 = -1e30f, mx1 = -1e30f;
        #pragma unroll
        for (int nt = 0; nt < 26; nt++) {
            #pragma unroll
            for (int idx = 0; idx < 4; idx++) {
                const int e = idx & 1, half = idx >> 1;
                const int col = nt * 8 + 2 * jq + e;
                const int row = row0 + half * 8;
                float s;
                if (col < LL) {
                    s = (sacc[nt][idx] + bias_mat[row * LPAD + col]) * scale;
                } else {
                    s = -1e30f;
                }
                sacc[nt][idx] = s;
                if (half == 0) mx0 = fmaxf(mx0, s); else mx1 = fmaxf(mx1, s);
            }
        }
        mx0 = fmaxf(mx0, __shfl_xor_sync(0xffffffffu, mx0, 1));
        mx0 = fmaxf(mx0, __shfl_xor_sync(0xffffffffu, mx0, 2));
        mx1 = fmaxf(mx1, __shfl_xor_sync(0xffffffffu, mx1, 1));
        mx1 = fmaxf(mx1, __shfl_xor_sync(0xffffffffu, mx1, 2));

        float sum0 = 0.f, sum1 = 0.f;
        #pragma unroll
        for (int nt = 0; nt < 26; nt++) {
            #pragma unroll
            for (int idx = 0; idx < 4; idx++) {
                const int e = idx & 1, half = idx >> 1;
                const int col = nt * 8 + 2 * jq + e;
                float p = 0.f;
                if (col < LL) {
                    p = __expf(sacc[nt][idx] - (half ? mx1 : mx0));
                    if (half == 0) sum0 += p; else sum1 += p;
                }
                sacc[nt][idx] = p;
            }
        }
        sum0 += __shfl_xor_sync(0xffffffffu, sum0, 1);
        sum0 += __shfl_xor_sync(0xffffffffu, sum0, 2);
        sum1 += __shfl_xor_sync(0xffffffffu, sum1, 1);
        sum1 += __shfl_xor_sync(0xffffffffu, sum1, 2);
        const float inv0 = 1.0f / sum0, inv1 = 1.0f / sum1;

        float oacc[4][4];
        #pragma unroll
        for (int nt = 0; nt < 4; nt++)
            #pragma unroll
            for (int e = 0; e < 4; e++) oacc[nt][e] = 0.f;

        #pragma unroll
        for (int kt = 0; kt < 13; kt++) {
            const uint32_t a0 = h2u(sacc[2 * kt][0],     sacc[2 * kt][1]);
            const uint32_t a1 = h2u(sacc[2 * kt][2],     sacc[2 * kt][3]);
            const uint32_t a2 = h2u(sacc[2 * kt + 1][0], sacc[2 * kt + 1][1]);
            const uint32_t a3 = h2u(sacc[2 * kt + 1][2], sacc[2 * kt + 1][3]);
            const int kb = kt * 8 + jq;
            #pragma unroll
            for (int nt = 0; nt < 4; nt++) {
                const int vr = (nt * 8 + r) * VTS5 + kb;
                const uint32_t b0 = vT[vr];
                const uint32_t b1 = vT[vr + 4];
                mma_fp16(oacc[nt], a0, a1, a2, a3, b0, b1);
            }
        }

        #pragma unroll
        for (int nt = 0; nt < 4; nt++) {
            #pragma unroll
            for (int idx = 0; idx < 4; idx++) {
                const int e = idx & 1, half = idx >> 1;
                const int row = row0 + half * 8;
                const int col = nt * 8 + 2 * jq + e;
                if (row < LL) {
                    const float vv = oacc[nt][idx] * (half ? inv1 : inv0);
                    o[base + (size_t)row * HID + col] = __float2half_rn(vv);
                }
            }
        }
    }
}

// ------------------------------------------------------------ fp16 TC GEMM
// C[M,N] = A[M,K] @ B[N,K]^T (+bias); 256x128 tile (A 256 rows, B 128 rows),
// 256 threads, 4x2 warp grid of 64x64 warp tiles, ldmatrix, 3-stage cp.async.
// One block/SM -> full per-SM L2 bandwidth; 24 KB load per k32 step.
//   mode 1: exact gelu -> Ch (half)    mode 2: (resid + val) * rate -> Cf
#define PSTR 20                              // uint32 stride per smem row
#define AROWS 256
#define BROWS 128
#define STAGE_U32 ((AROWS + BROWS) * PSTR)   // 7680 u32 = 30720 B
#define GSMEM (3 * STAGE_U32 * 4)            // 92160 B

__global__ __launch_bounds__(256) void gemm_fp16_kernel(
    const __half* __restrict__ A, const __half* __restrict__ B,
    const float* __restrict__ bias, const float* __restrict__ resid,
    float* __restrict__ Cf, __half* __restrict__ Ch,
    int M, int N, int K, int mode, float rate)
{
    extern __shared__ uint32_t smh[];
    const int tid  = threadIdx.x;
    const int lane = tid & 31, warp = tid >> 5;
    const int wr = warp >> 1, wc = warp & 1;     // 4x2 warp grid, 64x64 tiles
    const int bm = blockIdx.y * AROWS, bn = blockIdx.x * BROWS;

    const uint32_t smem_base = (uint32_t)__cvta_generic_to_shared(smh);
    const int nTiles = K / 32;

    auto load_tile = [&](int kt, int s) {
        const __half* Ag = A + (size_t)bm * K + (size_t)kt * 32;
        const __half* Bg = B + (size_t)bn * K + (size_t)kt * 32;
        const uint32_t sA = smem_base + (uint32_t)(s * STAGE_U32) * 4u;
        const uint32_t sB = sA + (uint32_t)(AROWS * PSTR) * 4u;
        #pragma unroll
        for (int i = 0; i < 4; i++) {                 // A: 256 rows
            const int idx = i * 256 + tid;
            const int r = idx >> 2, c = idx & 3;
            CP_ASYNC16(sA + (uint32_t)(r * PSTR * 4 + c * 16), Ag + (size_t)r * K + c * 8);
        }
        #pragma unroll
        for (int i = 0; i < 2; i++) {                 // B: 128 rows
            const int idx = i * 256 + tid;
            const int r = idx >> 2, c = idx & 3;
            CP_ASYNC16(sB + (uint32_t)(r * PSTR * 4 + c * 16), Bg + (size_t)r * K + c * 8);
        }
    };

    float acc[4][8][4];
    #pragma unroll
    for (int i = 0; i < 4; i++)
        #pragma unroll
        for (int j = 0; j < 8; j++)
            #pragma unroll
            for (int r = 0; r < 4; r++) acc[i][j][r] = 0.f;

    // ldmatrix per-lane base offsets (u32 index within stage)
    const int lrow = lane & 15;
    const int lkg  = (lane >> 4) * 4;
    const uint32_t aOff = (uint32_t)((wr * 64 + lrow) * PSTR + lkg);
    const uint32_t bOff = (uint32_t)(AROWS * PSTR + (wc * 64 + lrow) * PSTR + lkg);

    load_tile(0, 0);
    asm volatile("cp.async.commit_group;\n");
    if (nTiles > 1) {
        load_tile(1, 1);
        asm volatile("cp.async.commit_group;\n");
    }

    for (int t = 0; t < nTiles; t++) {
        if (t + 1 < nTiles) {
            asm volatile("cp.async.wait_group 1;\n");
        } else {
            asm volatile("cp.async.wait_group 0;\n");
        }
        __syncthreads();

        const uint32_t sb = smem_base + (uint32_t)((t % 3) * STAGE_U32) * 4u;

        #pragma unroll
        for (int ks = 0; ks < 2; ks++) {
            uint32_t a[4][4], b[4][4];
            #pragma unroll
            for (int mt = 0; mt < 4; mt++)
                LDSM_X4(a[mt], sb + (aOff + (uint32_t)(mt * 16 * PSTR) + ks * 8) * 4u);
            #pragma unroll
            for (int ntp = 0; ntp < 4; ntp++)
                LDSM_X4(b[ntp], sb + (bOff + (uint32_t)(ntp * 16 * PSTR) + ks * 8) * 4u);
            #pragma unroll
            for (int mt = 0; mt < 4; mt++) {
                #pragma unroll
                for (int nt = 0; nt < 8; nt++) {
                    const int ntp = nt >> 1, e = nt & 1;
                    mma_fp16(acc[mt][nt], a[mt][0], a[mt][1], a[mt][2], a[mt][3],
                             b[ntp][e], b[ntp][2 + e]);
                }
            }
        }

        if (t + 2 < nTiles) {
            load_tile(t + 2, (t + 2) % 3);
            asm volatile("cp.async.commit_group;\n");
        }
    }

    // ------------------------------------------------------------- epilogue
    const int cRow0 = bm + wr * 64 + (lane >> 2);
    const int cCol0 = bn + wc * 64 + 2 * (lane & 3);
    #pragma unroll
    for (int mt = 0; mt < 4; mt++) {
        #pragma unroll
        for (int nt = 0; nt < 8; nt++) {
            #pragma unroll
            for (int half = 0; half < 2; half++) {
                const int row = cRow0 + mt * 16 + half * 8;
                #pragma unroll
                for (int e = 0; e < 2; e++) {
                    const int col = cCol0 + nt * 8 + e;
                    float vv = acc[mt][nt][half * 2 + e];
                    if (bias) vv += bias[col];
                    if (mode == 1) {
                        vv = 0.5f * vv * (1.0f + erff(vv * 0.70710678118654752f));
                        Ch[(size_t)row * N + col] = __float2half_rn(vv);
                    } else {
                        vv = (resid[(size_t)row * N + col] + vv) * rate;
                        Cf[(size_t)row * N + col] = vv;
                    }
                }
            }
        }
    }
}

// --------------------------------------------------------------------- host
extern "C" void kernel_launch(void* const* d_in, const int* in_sizes, int n_in,
                              void* d_out, int out_size)
{
    const float* x        = (const float*)d_in[0];
    const float* rel_bias = (const float*)d_in[1];
    const float* wq       = (const float*)d_in[2];
    const float* wk       = (const float*)d_in[3];
    const float* wv       = (const float*)d_in[4];
    const float* w_out    = (const float*)d_in[5];
    const float* ln1_g    = (const float*)d_in[6];
    const float* ln1_b    = (const float*)d_in[7];
    const float* ln2_g    = (const float*)d_in[8];
    const float* ln2_b    = (const float*)d_in[9];
    const float* w1       = (const float*)d_in[10];
    const float* b1       = (const float*)d_in[11];
    const float* w2       = (const float*)d_in[12];
    const float* b2       = (const float*)d_in[13];
    float* out = (float*)d_out;

    float *p_bias;
    __half *p_qh, *p_kh, *p_vh, *p_oh, *p_lnh, *p_hh, *p_wouth, *p_w1h, *p_w2h;
    cudaGetSymbolAddress((void**)&p_bias, g_bias);
    cudaGetSymbolAddress((void**)&p_qh, g_qh);
    cudaGetSymbolAddress((void**)&p_kh, g_kh);
    cudaGetSymbolAddress((void**)&p_vh, g_vh);
    cudaGetSymbolAddress((void**)&p_oh,  g_oh);
    cudaGetSymbolAddress((void**)&p_lnh, g_lnh);
    cudaGetSymbolAddress((void**)&p_hh,  g_hh);
    cudaGetSymbolAddress((void**)&p_wouth, g_wouth);
    cudaGetSymbolAddress((void**)&p_w1h, g_w1h);
    cudaGetSymbolAddress((void**)&p_w2h, g_w2h);

    const int attn_smem = (2 * LPAD * QKS + 32 * VTS5) * 4;   // 47104
    cudaFuncSetAttribute(attn_fp16_kernel,
                         cudaFuncAttributeMaxDynamicSharedMemorySize, attn_smem);
    cudaFuncSetAttribute(gemm_fp16_kernel,
                         cudaFuncAttributeMaxDynamicSharedMemorySize, GSMEM);

    // 0) fused prep: fp16 weights + bias matrix (one launch)
    prep_kernel<<<(NPREP + 255) / 256, 256>>>(w_out, w1, w2, rel_bias,
                                              p_wouth, p_w1h, p_w2h, p_bias);

    // 1) fused ln1 + q/k/v projections (fp16 out)
    ln_qkv_kernel<<<M_ROWS, 256>>>(x, ln1_g, ln1_b, wq, wk, wv, p_qh, p_kh, p_vh);
    // 2) fp16 tensor-core attention -> fp16 o
    attn_fp16_kernel<<<NB * NH, 128, attn_smem>>>(p_qh, p_kh, p_vh, p_bias, p_oh);
    // 3) output projection + residual + rate -> d_out holds x1 (fp32)
    {
        dim3 grid(HID / BROWS, M_ROWS / AROWS);   // (6, 49)
        gemm_fp16_kernel<<<grid, 256, GSMEM>>>(p_oh, p_wouth, nullptr, x,
                                               out, nullptr,
                                               M_ROWS, HID, HID, 2, RATE_F);
    }
    // 4) ln2 -> fp16
    ln_kernel<<<M_ROWS, 256>>>(out, ln2_g, ln2_b, p_lnh);
    // 5) ffn1 + gelu -> fp16 hidden
    {
        dim3 grid(FF / BROWS, M_ROWS / AROWS);    // (24, 49)
        gemm_fp16_kernel<<<grid, 256, GSMEM>>>(p_lnh, p_w1h, b1, nullptr,
                                               nullptr, p_hh,
                                               M_ROWS, FF, HID, 1, 0.f);
    }
    // 6) ffn2 + residual + rate -> d_out final (fp32)
    {
        dim3 grid(HID / BROWS, M_ROWS / AROWS);   // (6, 49)
        gemm_fp16_kernel<<<grid, 256, GSMEM>>>(p_hh, p_w2h, b2, out,
                                               out, nullptr,
                                               M_ROWS, HID, FF, 2, RATE_F);
    }
}

// round 16
// speedup vs baseline: 1.0888x; 1.0888x over previous
#include <cuda_runtime.h>
#include <cuda_bf16.h>
#include <cuda_fp16.h>
#include <math.h>
#include <stdint.h>

// Problem constants
#define NB     64
#define LL     196
#define HID    768
#define FF     3072
#define NH     24
#define HD     32
#define M_ROWS (NB * LL)          // 12544
#define RATE_F 0.2f
#define LPAD   208

// ---------------- scratch (static device globals; no runtime allocation) ----
__device__ __half g_qh[(size_t)M_ROWS * HID];
__device__ __half g_kh[(size_t)M_ROWS * HID];
__device__ __half g_vh[(size_t)M_ROWS * HID];
__device__ __half g_oh [(size_t)M_ROWS * HID];
__device__ __half g_lnh[(size_t)M_ROWS * HID];
__device__ __half g_hh [(size_t)M_ROWS * FF];
__device__ __half g_wouth[HID * HID];
__device__ __half g_w1h[FF * HID];
__device__ __half g_w2h[HID * FF];
__device__ float  g_bias[LPAD * LPAD];

// ------------------------------------------------------------ helpers
__device__ __forceinline__ void mma_fp16(
    float* c, uint32_t a0, uint32_t a1, uint32_t a2, uint32_t a3,
    uint32_t b0, uint32_t b1)
{
    asm volatile(
        "mma.sync.aligned.m16n8k16.row.col.f32.f16.f16.f32 "
        "{%0,%1,%2,%3}, {%4,%5,%6,%7}, {%8,%9}, {%0,%1,%2,%3};\n"
        : "+f"(c[0]), "+f"(c[1]), "+f"(c[2]), "+f"(c[3])
        : "r"(a0), "r"(a1), "r"(a2), "r"(a3), "r"(b0), "r"(b1));
}
__device__ __forceinline__ uint32_t h2u(float lo, float hi) {
    __half2 h = __floats2half2_rn(lo, hi);
    return *reinterpret_cast<uint32_t*>(&h);
}

#define CP_ASYNC16(dst, src) \
    asm volatile("cp.async.cg.shared.global [%0], [%1], 16;\n" :: "r"(dst), "l"(src))

#define LDSM_X4(r, addr) \
    asm volatile("ldmatrix.sync.aligned.m8n8.x4.shared.b16 {%0,%1,%2,%3}, [%4];" \
        : "=r"((r)[0]), "=r"((r)[1]), "=r"((r)[2]), "=r"((r)[3]) : "r"(addr))

// ------------------------------------------- fused prep (weights + bias mat)
#define NW0 (HID * HID)
#define NW1 (FF * HID)
#define NW2 (HID * FF)
#define NPREP (NW0 + NW1 + NW2 + LPAD * LPAD)

__global__ __launch_bounds__(256) void prep_kernel(
    const float* __restrict__ w_out, const float* __restrict__ w1,
    const float* __restrict__ w2, const float* __restrict__ rel_bias,
    __half* __restrict__ wouth, __half* __restrict__ w1h,
    __half* __restrict__ w2h, float* __restrict__ bm)
{
    int i = blockIdx.x * 256 + threadIdx.x;
    if (i < NW0) { wouth[i] = __float2half_rn(w_out[i]); return; }
    i -= NW0;
    if (i < NW1) { w1h[i] = __float2half_rn(w1[i]); return; }
    i -= NW1;
    if (i < NW2) { w2h[i] = __float2half_rn(w2[i]); return; }
    i -= NW2;
    if (i < LPAD * LPAD) {
        int row = i / LPAD, col = i % LPAD;
        float val = 0.f;
        if (row < LL && col < LL) {
            int qi = row / 14, qj = row % 14;
            int ki = col / 14, kj = col % 14;
            val = rel_bias[(qi - ki + 14) * 28 + (qj - kj + 14)];
        }
        bm[i] = val;
    }
}

// --------------------------------------------- LayerNorm (fp16 out for GEMM)
__global__ __launch_bounds__(256) void ln_kernel(
    const float* __restrict__ x, const float* __restrict__ g,
    const float* __restrict__ b, __half* __restrict__ y)
{
    __shared__ float sm8[8];
    __shared__ float sstat;
    const int row = blockIdx.x, tid = threadIdx.x;
    const float* xr = x + (size_t)row * HID;
    float v0 = xr[tid], v1 = xr[tid + 256], v2 = xr[tid + 512];
    float s = v0 + v1 + v2;
    #pragma unroll
    for (int off = 16; off; off >>= 1) s += __shfl_xor_sync(0xffffffffu, s, off);
    if ((tid & 31) == 0) sm8[tid >> 5] = s;
    __syncthreads();
    if (tid == 0) {
        float t = 0.f;
        #pragma unroll
        for (int i = 0; i < 8; i++) t += sm8[i];
        sstat = t * (1.0f / HID);
    }
    __syncthreads();
    const float mu = sstat;
    float d0 = v0 - mu, d1 = v1 - mu, d2 = v2 - mu;
    float q = d0 * d0 + d1 * d1 + d2 * d2;
    #pragma unroll
    for (int off = 16; off; off >>= 1) q += __shfl_xor_sync(0xffffffffu, q, off);
    __syncthreads();
    if ((tid & 31) == 0) sm8[tid >> 5] = q;
    __syncthreads();
    if (tid == 0) {
        float t = 0.f;
        #pragma unroll
        for (int i = 0; i < 8; i++) t += sm8[i];
        sstat = rsqrtf(t * (1.0f / HID) + 1e-5f);
    }
    __syncthreads();
    const float r = sstat;
    __half* yr = y + (size_t)row * HID;
    yr[tid]       = __float2half_rn(d0 * r * g[tid]       + b[tid]);
    yr[tid + 256] = __float2half_rn(d1 * r * g[tid + 256] + b[tid + 256]);
    yr[tid + 512] = __float2half_rn(d2 * r * g[tid + 512] + b[tid + 512]);
}

// ------------------------------------------ fused LayerNorm1 + QKV (fp16 out)
__global__ __launch_bounds__(256) void ln_qkv_kernel(
    const float* __restrict__ x, const float* __restrict__ g,
    const float* __restrict__ b,
    const float* __restrict__ wq, const float* __restrict__ wk,
    const float* __restrict__ wv,
    __half* __restrict__ q, __half* __restrict__ k_, __half* __restrict__ v)
{
    __shared__ float xs[HID];
    __shared__ float ws[3][32][33];
    __shared__ float sm8[8];
    __shared__ float sstat;
    const int row = blockIdx.x, tid = threadIdx.x;

    for (int t = tid; t < 1024; t += 256) {
        const int e = t >> 5, d = t & 31;
        ws[0][e][d] = wq[t];
        ws[1][e][d] = wk[t];
        ws[2][e][d] = wv[t];
    }

    const float* xr = x + (size_t)row * HID;
    float v0 = xr[tid], v1 = xr[tid + 256], v2 = xr[tid + 512];
    float s = v0 + v1 + v2;
    #pragma unroll
    for (int off = 16; off; off >>= 1) s += __shfl_xor_sync(0xffffffffu, s, off);
    if ((tid & 31) == 0) sm8[tid >> 5] = s;
    __syncthreads();
    if (tid == 0) {
        float t = 0.f;
        #pragma unroll
        for (int i = 0; i < 8; i++) t += sm8[i];
        sstat = t * (1.0f / HID);
    }
    __syncthreads();
    const float mu = sstat;
    float d0 = v0 - mu, d1 = v1 - mu, d2 = v2 - mu;
    float qq = d0 * d0 + d1 * d1 + d2 * d2;
    #pragma unroll
    for (int off = 16; off; off >>= 1) qq += __shfl_xor_sync(0xffffffffu, qq, off);
    __syncthreads();
    if ((tid & 31) == 0) sm8[tid >> 5] = qq;
    __syncthreads();
    if (tid == 0) {
        float t = 0.f;
        #pragma unroll
        for (int i = 0; i < 8; i++) t += sm8[i];
        sstat = rsqrtf(t * (1.0f / HID) + 1e-5f);
    }
    __syncthreads();
    const float r = sstat;
    xs[tid]       = d0 * r * g[tid]       + b[tid];
    xs[tid + 256] = d1 * r * g[tid + 256] + b[tid + 256];
    xs[tid + 512] = d2 * r * g[tid + 512] + b[tid + 512];
    __syncthreads();

    for (int t = tid; t < 3 * HID; t += 256) {
        const int m = t / HID, rr = t % HID;
        const int hh = rr >> 5, e = rr & 31;
        const float* xp = xs + (hh << 5);
        const float* wp = &ws[m][e][0];
        float acc = 0.f;
        #pragma unroll
        for (int d = 0; d < 32; d++) acc = fmaf(xp[d], wp[d], acc);
        __half* out = (m == 0) ? q : ((m == 1) ? k_ : v);
        out[(size_t)row * HID + rr] = __float2half_rn(acc);
    }
}

// ------------------------------------------------ fp16 tensor-core attention
#define QKS  20    // uint32 stride per qs/ks row (40 halves)
#define VTS5 108   // uint32 stride per vT row (216 halves)

__global__ __launch_bounds__(128, 3) void attn_fp16_kernel(
    const __half* __restrict__ q, const __half* __restrict__ k,
    const __half* __restrict__ v, const float* __restrict__ bias_mat,
    __half* __restrict__ o)
{
    extern __shared__ uint32_t smA[];
    uint32_t* qs = smA;
    uint32_t* ks = qs + LPAD * QKS;
    uint32_t* vT = ks + LPAD * QKS;

    const int nb = blockIdx.x;
    const int n = nb / NH, h = nb % NH;
    const int tid = threadIdx.x, lane = tid & 31, warp = tid >> 5;
    const size_t base = (size_t)n * LL * HID + (size_t)h * HD;

    {
        const uint32_t* qg = (const uint32_t*)(q + base);
        const uint32_t* kg = (const uint32_t*)(k + base);
        for (int t = tid; t < LL * 16; t += 128) {
            const int l = t >> 4, dp = t & 15;
            qs[l * QKS + dp] = qg[l * (HID / 2) + dp];
            ks[l * QKS + dp] = kg[l * (HID / 2) + dp];
        }
        __half* vh = (__half*)vT;
        for (int t = tid; t < LL * HD; t += 128) {
            const int l = t >> 5, d = t & 31;
            vh[d * 216 + l] = v[base + (size_t)l * HID + d];
        }
        for (int t = tid; t < 12 * 16; t += 128)
            qs[(LL + (t >> 4)) * QKS + (t & 15)] = 0;
        for (int t = tid; t < 32 * 12; t += 128)
            vh[(t / 12) * 216 + LL + (t % 12)] = __float2half_rn(0.f);
    }
    __syncthreads();

    const float scale = 0.17677669529663687f;
    const int r = lane >> 2, jq = lane & 3;

    for (int mt = warp; mt < 13; mt += 4) {
        const int row0 = mt * 16 + r;

        float sacc[26][4];
        #pragma unroll
        for (int nt = 0; nt < 26; nt++)
            #pragma unroll
            for (int e = 0; e < 4; e++) sacc[nt][e] = 0.f;

        #pragma unroll
        for (int kt = 0; kt < 2; kt++) {
            const int kb = kt * 8 + jq;
            const uint32_t a0 = qs[row0 * QKS + kb];
            const uint32_t a1 = qs[(row0 + 8) * QKS + kb];
            const uint32_t a2 = qs[row0 * QKS + kb + 4];
            const uint32_t a3 = qs[(row0 + 8) * QKS + kb + 4];
            #pragma unroll
            for (int nt = 0; nt < 26; nt++) {
                const int kr = (nt * 8 + r) * QKS + kb;
                const uint32_t b0 = ks[kr];
                const uint32_t b1 = ks[kr + 4];
                mma_fp16(sacc[nt], a0, a1, a2, a3, b0, b1);
            }
        }

        float mx0 = -1e30f, mx1 = -1e30f;
        #pragma unroll
        for (int nt = 0; nt < 26; nt++) {
            #pragma unroll
            for (int idx = 0; idx < 4; idx++) {
                const int e = idx & 1, half = idx >> 1;
                const int col = nt * 8 + 2 * jq + e;
                const int row = row0 + half * 8;
                float s;
                if (col < LL) {
                    s = (sacc[nt][idx] + bias_mat[row * LPAD + col]) * scale;
                } else {
                    s = -1e30f;
                }
                sacc[nt][idx] = s;
                if (half == 0) mx0 = fmaxf(mx0, s); else mx1 = fmaxf(mx1, s);
            }
        }
        mx0 = fmaxf(mx0, __shfl_xor_sync(0xffffffffu, mx0, 1));
        mx0 = fmaxf(mx0, __shfl_xor_sync(0xffffffffu, mx0, 2));
        mx1 = fmaxf(mx1, __shfl_xor_sync(0xffffffffu, mx1, 1));
        mx1 = fmaxf(mx1, __shfl_xor_sync(0xffffffffu, mx1, 2));

        float sum0 = 0.f, sum1 = 0.f;
        #pragma unroll
        for (int nt = 0; nt < 26; nt++) {
            #pragma unroll
            for (int idx = 0; idx < 4; idx++) {
                const int e = idx & 1, half = idx >> 1;
                const int col = nt * 8 + 2 * jq + e;
                float p = 0.f;
                if (col < LL) {
                    p = __expf(sacc[nt][idx] - (half ? mx1 : mx0));
                    if (half == 0) sum0 += p; else sum1 += p;
                }
                sacc[nt][idx] = p;
            }
        }
        sum0 += __shfl_xor_sync(0xffffffffu, sum0, 1);
        sum0 += __shfl_xor_sync(0xffffffffu, sum0, 2);
        sum1 += __shfl_xor_sync(0xffffffffu, sum1, 1);
        sum1 += __shfl_xor_sync(0xffffffffu, sum1, 2);
        const float inv0 = 1.0f / sum0, inv1 = 1.0f / sum1;

        float oacc[4][4];
        #pragma unroll
        for (int nt = 0; nt < 4; nt++)
            #pragma unroll
            for (int e = 0; e < 4; e++) oacc[nt][e] = 0.f;

        #pragma unroll
        for (int kt = 0; kt < 13; kt++) {
            const uint32_t a0 = h2u(sacc[2 * kt][0],     sacc[2 * kt][1]);
            const uint32_t a1 = h2u(sacc[2 * kt][2],     sacc[2 * kt][3]);
            const uint32_t a2 = h2u(sacc[2 * kt + 1][0], sacc[2 * kt + 1][1]);
            const uint32_t a3 = h2u(sacc[2 * kt + 1][2], sacc[2 * kt + 1][3]);
            const int kb = kt * 8 + jq;
            #pragma unroll
            for (int nt = 0; nt < 4; nt++) {
                const int vr = (nt * 8 + r) * VTS5 + kb;
                const uint32_t b0 = vT[vr];
                const uint32_t b1 = vT[vr + 4];
                mma_fp16(oacc[nt], a0, a1, a2, a3, b0, b1);
            }
        }

        #pragma unroll
        for (int nt = 0; nt < 4; nt++) {
            #pragma unroll
            for (int idx = 0; idx < 4; idx++) {
                const int e = idx & 1, half = idx >> 1;
                const int row = row0 + half * 8;
                const int col = nt * 8 + 2 * jq + e;
                if (row < LL) {
                    const float vv = oacc[nt][idx] * (half ? inv1 : inv0);
                    o[base + (size_t)row * HID + col] = __float2half_rn(vv);
                }
            }
        }
    }
}

// ------------------------------------------------------------ fp16 TC GEMM
// C[M,N] = A[M,K] @ B[N,K]^T (+bias); 128x128 tile, 256 threads (4x2 warps,
// 32x64 warp tiles), ldmatrix, 4-stage cp.async (stage = t & 3), 2 blocks/SM.
//   mode 1: exact gelu -> Ch (half)    mode 2: (resid + val) * rate -> Cf
#define PSTR 20                        // uint32 stride per smem row
#define STAGE_U32 (2 * 128 * PSTR)     // 5120 u32 = 20 KB per stage
#define GSMEM (4 * STAGE_U32 * 4)      // 81920 B

__global__ __launch_bounds__(256, 2) void gemm_fp16_kernel(
    const __half* __restrict__ A, const __half* __restrict__ B,
    const float* __restrict__ bias, const float* __restrict__ resid,
    float* __restrict__ Cf, __half* __restrict__ Ch,
    int M, int N, int K, int mode, float rate)
{
    extern __shared__ uint32_t smh[];
    const int tid  = threadIdx.x;
    const int lane = tid & 31, warp = tid >> 5;
    const int wr = warp >> 1, wc = warp & 1;
    const int bm = blockIdx.y * 128, bn = blockIdx.x * 128;

    const uint32_t smem_base = (uint32_t)__cvta_generic_to_shared(smh);
    const int nTiles = K / 32;

    // per-thread load source pointers (hoisted; advance by 32 halves per tile)
    const int ldr = tid >> 2, ldc = tid & 3;
    const __half* Ald = A + (size_t)(bm + ldr) * K + ldc * 8;
    const __half* Al2 = A + (size_t)(bm + 64 + ldr) * K + ldc * 8;
    const __half* Bld = B + (size_t)(bn + ldr) * K + ldc * 8;
    const __half* Bl2 = B + (size_t)(bn + 64 + ldr) * K + ldc * 8;
    const uint32_t dOffA  = (uint32_t)(ldr * PSTR * 4 + ldc * 16);
    const uint32_t dOffA2 = dOffA + (uint32_t)(64 * PSTR * 4);
    const uint32_t dOffB  = dOffA + (uint32_t)(128 * PSTR * 4);
    const uint32_t dOffB2 = dOffB + (uint32_t)(64 * PSTR * 4);

    auto load_tile = [&](int kt, int s) {
        const uint32_t sb = smem_base + (uint32_t)(s * STAGE_U32) * 4u;
        const size_t koff = (size_t)kt * 32;
        CP_ASYNC16(sb + dOffA,  Ald + koff);
        CP_ASYNC16(sb + dOffA2, Al2 + koff);
        CP_ASYNC16(sb + dOffB,  Bld + koff);
        CP_ASYNC16(sb + dOffB2, Bl2 + koff);
    };

    float acc[2][8][4];
    #pragma unroll
    for (int i = 0; i < 2; i++)
        #pragma unroll
        for (int j = 0; j < 8; j++)
            #pragma unroll
            for (int r = 0; r < 4; r++) acc[i][j][r] = 0.f;

    // ldmatrix per-lane base offsets (u32 index within stage)
    const int lrow = lane & 15;
    const int lkg  = (lane >> 4) * 4;
    const uint32_t aOff = (uint32_t)((wr * 32 + lrow) * PSTR + lkg);
    const uint32_t bOff = (uint32_t)(128 * PSTR + (wc * 64 + lrow) * PSTR + lkg);

    load_tile(0, 0);
    asm volatile("cp.async.commit_group;\n");
    if (nTiles > 1) { load_tile(1, 1); asm volatile("cp.async.commit_group;\n"); }
    if (nTiles > 2) { load_tile(2, 2); asm volatile("cp.async.commit_group;\n"); }

    for (int t = 0; t < nTiles; t++) {
        const int rem = nTiles - 1 - t;
        if (rem >= 2)      asm volatile("cp.async.wait_group 2;\n");
        else if (rem == 1) asm volatile("cp.async.wait_group 1;\n");
        else               asm volatile("cp.async.wait_group 0;\n");
        __syncthreads();

        const uint32_t sb = smem_base + (uint32_t)((t & 3) * STAGE_U32) * 4u;

        #pragma unroll
        for (int ks = 0; ks < 2; ks++) {
            uint32_t a[2][4], b[4][4];
            LDSM_X4(a[0], sb + (aOff + ks * 8) * 4u);
            LDSM_X4(a[1], sb + (aOff + 16 * PSTR + ks * 8) * 4u);
            #pragma unroll
            for (int ntp = 0; ntp < 4; ntp++)
                LDSM_X4(b[ntp], sb + (bOff + (uint32_t)(ntp * 16 * PSTR) + ks * 8) * 4u);
            #pragma unroll
            for (int mt = 0; mt < 2; mt++) {
                #pragma unroll
                for (int nt = 0; nt < 8; nt++) {
                    const int ntp = nt >> 1, e = nt & 1;
                    mma_fp16(acc[mt][nt], a[mt][0], a[mt][1], a[mt][2], a[mt][3],
                             b[ntp][e], b[ntp][2 + e]);
                }
            }
        }

        if (t + 3 < nTiles) {
            load_tile(t + 3, (t + 3) & 3);
            asm volatile("cp.async.commit_group;\n");
        }
    }

    // ------------------------------------------------------------- epilogue
    const int cRow0 = bm + wr * 32 + (lane >> 2);
    const int cCol0 = bn + wc * 64 + 2 * (lane & 3);
    #pragma unroll
    for (int mt = 0; mt < 2; mt++) {
        #pragma unroll
        for (int nt = 0; nt < 8; nt++) {
            #pragma unroll
            for (int half = 0; half < 2; half++) {
                const int row = cRow0 + mt * 16 + half * 8;
                #pragma unroll
                for (int e = 0; e < 2; e++) {
                    const int col = cCol0 + nt * 8 + e;
                    float vv = acc[mt][nt][half * 2 + e];
                    if (bias) vv += bias[col];
                    if (mode == 1) {
                        vv = 0.5f * vv * (1.0f + erff(vv * 0.70710678118654752f));
                        Ch[(size_t)row * N + col] = __float2half_rn(vv);
                    } else {
                        vv = (resid[(size_t)row * N + col] + vv) * rate;
                        Cf[(size_t)row * N + col] = vv;
                    }
                }
            }
        }
    }
}

// --------------------------------------------------------------------- host
extern "C" void kernel_launch(void* const* d_in, const int* in_sizes, int n_in,
                              void* d_out, int out_size)
{
    const float* x        = (const float*)d_in[0];
    const float* rel_bias = (const float*)d_in[1];
    const float* wq       = (const float*)d_in[2];
    const float* wk       = (const float*)d_in[3];
    const float* wv       = (const float*)d_in[4];
    const float* w_out    = (const float*)d_in[5];
    const float* ln1_g    = (const float*)d_in[6];
    const float* ln1_b    = (const float*)d_in[7];
    const float* ln2_g    = (const float*)d_in[8];
    const float* ln2_b    = (const float*)d_in[9];
    const float* w1       = (const float*)d_in[10];
    const float* b1       = (const float*)d_in[11];
    const float* w2       = (const float*)d_in[12];
    const float* b2       = (const float*)d_in[13];
    float* out = (float*)d_out;

    float *p_bias;
    __half *p_qh, *p_kh, *p_vh, *p_oh, *p_lnh, *p_hh, *p_wouth, *p_w1h, *p_w2h;
    cudaGetSymbolAddress((void**)&p_bias, g_bias);
    cudaGetSymbolAddress((void**)&p_qh, g_qh);
    cudaGetSymbolAddress((void**)&p_kh, g_kh);
    cudaGetSymbolAddress((void**)&p_vh, g_vh);
    cudaGetSymbolAddress((void**)&p_oh,  g_oh);
    cudaGetSymbolAddress((void**)&p_lnh, g_lnh);
    cudaGetSymbolAddress((void**)&p_hh,  g_hh);
    cudaGetSymbolAddress((void**)&p_wouth, g_wouth);
    cudaGetSymbolAddress((void**)&p_w1h, g_w1h);
    cudaGetSymbolAddress((void**)&p_w2h, g_w2h);

    const int attn_smem = (2 * LPAD * QKS + 32 * VTS5) * 4;   // 47104
    cudaFuncSetAttribute(attn_fp16_kernel,
                         cudaFuncAttributeMaxDynamicSharedMemorySize, attn_smem);
    cudaFuncSetAttribute(gemm_fp16_kernel,
                         cudaFuncAttributeMaxDynamicSharedMemorySize, GSMEM);

    // 0) fused prep: fp16 weights + bias matrix (one launch)
    prep_kernel<<<(NPREP + 255) / 256, 256>>>(w_out, w1, w2, rel_bias,
                                              p_wouth, p_w1h, p_w2h, p_bias);

    // 1) fused ln1 + q/k/v projections (fp16 out)
    ln_qkv_kernel<<<M_ROWS, 256>>>(x, ln1_g, ln1_b, wq, wk, wv, p_qh, p_kh, p_vh);
    // 2) fp16 tensor-core attention -> fp16 o
    attn_fp16_kernel<<<NB * NH, 128, attn_smem>>>(p_qh, p_kh, p_vh, p_bias, p_oh);
    // 3) output projection + residual + rate -> d_out holds x1 (fp32)
    {
        dim3 grid(HID / 128, M_ROWS / 128);
        gemm_fp16_kernel<<<grid, 256, GSMEM>>>(p_oh, p_wouth, nullptr, x,
                                               out, nullptr,
                                               M_ROWS, HID, HID, 2, RATE_F);
    }
    // 4) ln2 -> fp16
    ln_kernel<<<M_ROWS, 256>>>(out, ln2_g, ln2_b, p_lnh);
    // 5) ffn1 + gelu -> fp16 hidden
    {
        dim3 grid(FF / 128, M_ROWS / 128);
        gemm_fp16_kernel<<<grid, 256, GSMEM>>>(p_lnh, p_w1h, b1, nullptr,
                                               nullptr, p_hh,
                                               M_ROWS, FF, HID, 1, 0.f);
    }
    // 6) ffn2 + residual + rate -> d_out final (fp32)
    {
        dim3 grid(HID / 128, M_ROWS / 128);
        gemm_fp16_kernel<<<grid, 256, GSMEM>>>(p_hh, p_w2h, b2, out,
                                               out, nullptr,
                                               M_ROWS, HID, FF, 2, RATE_F);
    }
}